// round 15
// baseline (speedup 1.0000x reference)
#include <cuda_runtime.h>
#include <cuda_fp16.h>

// Problem constants
#define B_  256
#define I_  128
#define J_  128
#define H_  32
#define FP_ 8            // padded feature count; f7 = 1.0 bias lane
#define ITILE 2
#define IBLKS (I_ / ITILE)   // 64

// Prep-kernel region boundaries (blocks of 256 threads)
#define PREP_A 2048      // w1 fragments: I*J*32 uint4 / 256
#define PREP_B (PREP_A + 256)    // w2 fragments: I*J*4 uint4 / 256
#define PREP_C (PREP_B + 32)     // bsum: IBLKS*J / 256
#define PREP_D (PREP_C + 128)    // feats + zero out: B*I / 256

// Scratch (allocation-free rule: __device__ globals)
__device__ __align__(16) __half g_feats_h[I_ * B_ * FP_];  // [i][b][f0..f7]
__device__ __align__(16) uint4  g_w1p[I_ * J_ * 32];       // 8 MB packed W1/B1 fragments
__device__ __align__(16) uint4  g_w2p[I_ * J_ * 4];        // 1 MB packed W2 fragments
__device__ float g_bsum[IBLKS * J_];                       // per-(ib,j) Sum(B2)

__device__ __forceinline__ unsigned u32h2(__half2 h) {
    return *reinterpret_cast<unsigned*>(&h);
}
__device__ __forceinline__ unsigned hfma2u(unsigned a, unsigned b, unsigned c) {
    unsigned d;
    asm("fma.rn.f16x2 %0, %1, %2, %3;" : "=r"(d) : "r"(a), "r"(b), "r"(c));
    return d;
}
__device__ __forceinline__ unsigned tanh2u(unsigned a) {
    unsigned d;
    asm("tanh.approx.f16x2 %0, %1;" : "=r"(d) : "r"(a));
    return d;
}

// Kernel 1 (prep): packs weights into fragment layout + feats + zeroes out.
// Region A: g_w1p[ij*32 + gid*4 + p] .q = half2(0.5*W1[i,j,h=q*8+gid,2p],
//                                               0.5*(p<3 ? W1[...,2p+1] : B1[i,j,h]))
// Region B: g_w2p[ij*4 + tg] .q = half2(W2[h=q*8+tg*2], W2[h+1])
// Region C: g_bsum[ib*J+j] = B2[2ib,j] + B2[2ib+1,j]
// Region D: feats + out[t]=0
__global__ __launch_bounds__(256) void prep_kernel(
    const float* __restrict__ x,
    const float* __restrict__ W1,   // [I,J,H,7]
    const float* __restrict__ W2,   // [I,J,1,H]
    const float* __restrict__ B1,   // [I,J,H]
    const float* __restrict__ B2,   // [I,J,1]
    float* __restrict__ out)
{
    const int bid = blockIdx.x;
    const int tid = threadIdx.x;

    if (bid < PREP_A) {
        // W1/B1 fragment packing
        int u  = bid * 256 + tid;        // uint4 index
        int ij = u >> 5;
        int r  = u & 31;
        int gid = r >> 2;
        int p   = r & 3;
        const float* w1b = W1 + (size_t)ij * (H_ * 7);
        const float* b1b = B1 + (size_t)ij * H_;
        unsigned w[4];
        #pragma unroll
        for (int q = 0; q < 4; q++) {
            int h = q * 8 + gid;
            float lo = 0.5f * w1b[h * 7 + 2 * p];
            float hi = 0.5f * ((p < 3) ? w1b[h * 7 + 2 * p + 1] : b1b[h]);
            w[q] = u32h2(__floats2half2_rn(lo, hi));
        }
        g_w1p[u] = make_uint4(w[0], w[1], w[2], w[3]);
    } else if (bid < PREP_B) {
        // W2 fragment packing
        int v  = (bid - PREP_A) * 256 + tid;   // uint4 index
        int ij = v >> 2;
        int tg = v & 3;
        const float* w2b = W2 + (size_t)ij * H_;
        unsigned w[4];
        #pragma unroll
        for (int q = 0; q < 4; q++) {
            int h = q * 8 + tg * 2;
            w[q] = u32h2(__floats2half2_rn(w2b[h], w2b[h + 1]));
        }
        g_w2p[v] = make_uint4(w[0], w[1], w[2], w[3]);
    } else if (bid < PREP_C) {
        // bias sums per (ib, j)
        int w  = (bid - PREP_B) * 256 + tid;
        int ib = w >> 7;
        int j  = w & 127;
        g_bsum[w] = B2[(size_t)(2 * ib) * J_ + j] + B2[(size_t)(2 * ib + 1) * J_ + j];
    } else {
        // feats + zero out
        int t = (bid - PREP_C) * 256 + tid;    // t = b*I + i
        out[t] = 0.0f;
        int b = t >> 7, i = t & 127;
        float xi = x[t];                       // coalesced
        float s1, c1, s2, c2, s4, c4;
        __sincosf(xi, &s1, &c1);
        __sincosf(2.0f * xi, &s2, &c2);
        __sincosf(4.0f * xi, &s4, &c4);
        __half2 p0 = __floats2half2_rn(xi, s1);
        __half2 p1 = __floats2half2_rn(s2, s4);
        __half2 p2 = __floats2half2_rn(c1, c2);
        __half2 p3 = __floats2half2_rn(c4, 1.0f);   // f7 = bias lane
        uint4 v = make_uint4(u32h2(p0), u32h2(p1), u32h2(p2), u32h2(p3));
        *reinterpret_cast<uint4*>(&g_feats_h[((size_t)i * B_ + b) * FP_]) = v;
    }
}

// Kernel 2: block = (i-tile of 2, j), 256 threads (8 warps), 8192 blocks.
// NO smem, NO syncthreads, NO staging: all operands are pre-packed fragments
// loaded straight from gmem (L1 broadcasts the weight fragments across the
// block's 8 warps). Math identical to R7-R14.
__global__ void __launch_bounds__(256, 7) kan_main_kernel(float* __restrict__ out)
{
    const int j   = blockIdx.y;
    const int ib  = blockIdx.x;
    const int i0  = ib * ITILE;
    const int tid = threadIdx.x;

    const int lane = tid & 31, warp = tid >> 5;
    const int gid = lane >> 2;      // fragment row selector
    const int tig = lane & 3;       // fragment col selector
    const int wbase = warp * 32;    // 8 warps x 32 b-rows

    const float bsum = g_bsum[ib * J_ + j];

    float acc[2][4] = {};           // [m-tile][k16-MMA D regs]
    const unsigned zero = 0;

    const __half* fbase = g_feats_h + (size_t)i0 * (B_ * FP_)
                        + (wbase + gid) * FP_ + tig * 2;

    #pragma unroll
    for (int il = 0; il < ITILE; il++) {
        const int ij = (i0 + il) * J_ + j;

        // Weight fragments: one LDG.128 each (shared across warps via L1)
        uint4 wq = g_w1p[ij * 32 + gid * 4 + tig];  // x..w = wf for h-groups 0..3
        uint4 bq = g_w2p[ij * 4 + tig];             // x..w = wb for h-groups 0..3

        // A fragments for both m-tiles (coalesced; L2-hot)
        const __half* fi = fbase + il * (B_ * FP_);
        unsigned A0[2], A1[2];
        #pragma unroll
        for (int mt = 0; mt < 2; mt++) {
            A0[mt] = *reinterpret_cast<const unsigned*>(fi + mt * 16 * FP_);
            A1[mt] = *reinterpret_cast<const unsigned*>(fi + (mt * 16 + 8) * FP_);
        }

        #pragma unroll
        for (int hgp = 0; hgp < 2; hgp++) {
            unsigned wf0 = hgp ? wq.z : wq.x;
            unsigned wf1 = hgp ? wq.w : wq.y;
            unsigned wb0 = hgp ? bq.z : bq.x;
            unsigned wb1 = hgp ? bq.w : bq.y;

            #pragma unroll
            for (int mt = 0; mt < 2; mt++) {
                // u-MMA, fp16 accumulator: D regs are f16x2
                unsigned u0, u1, u2, u3;
                asm volatile(
                    "mma.sync.aligned.m16n8k8.row.col.f16.f16.f16.f16 "
                    "{%0,%1}, {%2,%3}, {%4}, {%5,%6};"
                    : "=r"(u0), "=r"(u1)
                    : "r"(A0[mt]), "r"(A1[mt]), "r"(wf0), "r"(zero), "r"(zero));
                asm volatile(
                    "mma.sync.aligned.m16n8k8.row.col.f16.f16.f16.f16 "
                    "{%0,%1}, {%2,%3}, {%4}, {%5,%6};"
                    : "=r"(u2), "=r"(u3)
                    : "r"(A0[mt]), "r"(A1[mt]), "r"(wf1), "r"(zero), "r"(zero));

                // silu(t) = u + u*tanh(u), u = t/2 — pure f16x2
                unsigned s0 = hfma2u(u0, tanh2u(u0), u0);
                unsigned s1 = hfma2u(u1, tanh2u(u1), u1);
                unsigned s2 = hfma2u(u2, tanh2u(u2), u2);
                unsigned s3 = hfma2u(u3, tanh2u(u3), u3);

                // h-contraction: m16n8k16, B = W2 replicated over n, fp32 acc
                asm volatile(
                    "mma.sync.aligned.m16n8k16.row.col.f32.f16.f16.f32 "
                    "{%0,%1,%2,%3}, {%4,%5,%6,%7}, {%8,%9}, {%0,%1,%2,%3};"
                    : "+f"(acc[mt][0]), "+f"(acc[mt][1]),
                      "+f"(acc[mt][2]), "+f"(acc[mt][3])
                    : "r"(s0), "r"(s1), "r"(s2), "r"(s3), "r"(wb0), "r"(wb1));
            }
        }
    }

    // Epilogue: tig==0 lanes hold per-b sums. Atomic-accumulate into out[b*J + j].
    if (tig == 0) {
        #pragma unroll
        for (int mt = 0; mt < 2; mt++) {
            int brow = wbase + mt * 16 + gid;
            atomicAdd(&out[(size_t)brow * J_ + j],       acc[mt][0] + bsum);
            atomicAdd(&out[(size_t)(brow + 8) * J_ + j], acc[mt][2] + bsum);
        }
    }
}

extern "C" void kernel_launch(void* const* d_in, const int* in_sizes, int n_in,
                              void* d_out, int out_size) {
    const float* x  = (const float*)d_in[0];
    const float* W1 = (const float*)d_in[1];
    const float* W2 = (const float*)d_in[2];
    const float* B1 = (const float*)d_in[3];
    const float* B2 = (const float*)d_in[4];
    float* out = (float*)d_out;

    prep_kernel<<<PREP_D, 256>>>(x, W1, W2, B1, B2, out);
    kan_main_kernel<<<dim3(IBLKS, J_), 256>>>(out);
}

// round 16
// speedup vs baseline: 1.1932x; 1.1932x over previous
#include <cuda_runtime.h>
#include <cuda_fp16.h>

// Problem constants
#define B_  256
#define I_  128
#define J_  128
#define H_  32
#define FP_ 8            // padded feature count; f7 = 1.0 bias lane
#define ITILE 2
#define IBLKS (I_ / ITILE)   // 64

// Prep-kernel region boundaries (blocks of 256 threads)
#define PREP_A 2048      // w1 fragments: I*J*32 uint4 / 256
#define PREP_B (PREP_A + 256)    // w2 fragments: I*J*4 uint4 / 256
#define PREP_C (PREP_B + 32)     // bsum: IBLKS*J / 256
#define PREP_D (PREP_C + 128)    // feats + zero out: B*I / 256

// Scratch (allocation-free rule: __device__ globals)
__device__ __align__(16) __half g_feats_h[I_ * B_ * FP_];  // [i][b][f0..f7]
__device__ __align__(16) uint4  g_w1p[I_ * J_ * 32];       // packed W1/B1 fragments
__device__ __align__(16) uint4  g_w2p[I_ * J_ * 4];        // packed W2 fragments
__device__ float g_bsum[IBLKS * J_];                       // per-(ib,j) Sum(B2)

__device__ __forceinline__ unsigned u32h2(__half2 h) {
    return *reinterpret_cast<unsigned*>(&h);
}
__device__ __forceinline__ __half2 h2u(unsigned u) {
    return *reinterpret_cast<__half2*>(&u);
}
__device__ __forceinline__ unsigned hfma2u(unsigned a, unsigned b, unsigned c) {
    unsigned d;
    asm("fma.rn.f16x2 %0, %1, %2, %3;" : "=r"(d) : "r"(a), "r"(b), "r"(c));
    return d;
}
__device__ __forceinline__ unsigned tanh2u(unsigned a) {
    unsigned d;
    asm("tanh.approx.f16x2 %0, %1;" : "=r"(d) : "r"(a));
    return d;
}

// silu via FMA-pipe polynomial: s = u + u*tanh(u), tanh(u) ~= uc*q(uc^2),
// uc = clamp(u, +-1.2998), q deg-3 in v (odd deg-7 overall).
// Collocated at u = 0.2, 0.6, 0.95, 1.3 (exact at clamp boundary).
__device__ __forceinline__ unsigned silu_poly(unsigned uu,
                                              __half2 C1, __half2 C3,
                                              __half2 C5, __half2 C7,
                                              __half2 CLP, __half2 CLN) {
    __half2 u  = h2u(uu);
    __half2 uc = __hmin2(__hmax2(u, CLN), CLP);            // alu pipe
    __half2 v  = __hmul2(uc, uc);
    __half2 q  = __hfma2(__hfma2(__hfma2(C7, v, C5), v, C3), v, C1);
    __half2 m  = __hmul2(u, uc);                            // = u*uc (>=0)
    __half2 s  = __hfma2(m, q, u);                          // u + u*tanh(uc)
    return u32h2(s);
}

// Kernel 1 (prep): packs weights into fragment layout + feats + zeroes out.
__global__ __launch_bounds__(256) void prep_kernel(
    const float* __restrict__ x,
    const float* __restrict__ W1,   // [I,J,H,7]
    const float* __restrict__ W2,   // [I,J,1,H]
    const float* __restrict__ B1,   // [I,J,H]
    const float* __restrict__ B2,   // [I,J,1]
    float* __restrict__ out)
{
    const int bid = blockIdx.x;
    const int tid = threadIdx.x;

    if (bid < PREP_A) {
        // W1/B1 fragment packing
        int u  = bid * 256 + tid;        // uint4 index
        int ij = u >> 5;
        int r  = u & 31;
        int gid = r >> 2;
        int p   = r & 3;
        const float* w1b = W1 + (size_t)ij * (H_ * 7);
        const float* b1b = B1 + (size_t)ij * H_;
        unsigned w[4];
        #pragma unroll
        for (int q = 0; q < 4; q++) {
            int h = q * 8 + gid;
            float lo = 0.5f * w1b[h * 7 + 2 * p];
            float hi = 0.5f * ((p < 3) ? w1b[h * 7 + 2 * p + 1] : b1b[h]);
            w[q] = u32h2(__floats2half2_rn(lo, hi));
        }
        g_w1p[u] = make_uint4(w[0], w[1], w[2], w[3]);
    } else if (bid < PREP_B) {
        // W2 fragment packing
        int v  = (bid - PREP_A) * 256 + tid;   // uint4 index
        int ij = v >> 2;
        int tg = v & 3;
        const float* w2b = W2 + (size_t)ij * H_;
        unsigned w[4];
        #pragma unroll
        for (int q = 0; q < 4; q++) {
            int h = q * 8 + tg * 2;
            w[q] = u32h2(__floats2half2_rn(w2b[h], w2b[h + 1]));
        }
        g_w2p[v] = make_uint4(w[0], w[1], w[2], w[3]);
    } else if (bid < PREP_C) {
        // bias sums per (ib, j)
        int w  = (bid - PREP_B) * 256 + tid;
        int ib = w >> 7;
        int j  = w & 127;
        g_bsum[w] = B2[(size_t)(2 * ib) * J_ + j] + B2[(size_t)(2 * ib + 1) * J_ + j];
    } else {
        // feats + zero out
        int t = (bid - PREP_C) * 256 + tid;    // t = b*I + i
        out[t] = 0.0f;
        int b = t >> 7, i = t & 127;
        float xi = x[t];                       // coalesced
        float s1, c1, s2, c2, s4, c4;
        __sincosf(xi, &s1, &c1);
        __sincosf(2.0f * xi, &s2, &c2);
        __sincosf(4.0f * xi, &s4, &c4);
        __half2 p0 = __floats2half2_rn(xi, s1);
        __half2 p1 = __floats2half2_rn(s2, s4);
        __half2 p2 = __floats2half2_rn(c1, c2);
        __half2 p3 = __floats2half2_rn(c4, 1.0f);   // f7 = bias lane
        uint4 v = make_uint4(u32h2(p0), u32h2(p1), u32h2(p2), u32h2(p3));
        *reinterpret_cast<uint4*>(&g_feats_h[((size_t)i * B_ + b) * FP_]) = v;
    }
}

// Kernel 2: block = (i-tile of 2, j), 256 threads (8 warps), 8192 blocks.
// Smem-free, staged-fragment loads, occ ~91%. silu split across pipes:
// pairs (u0,u1) -> FMA-pipe polynomial, pairs (u2,u3) -> XU tanh.approx.
__global__ void __launch_bounds__(256, 7) kan_main_kernel(float* __restrict__ out)
{
    const int j   = blockIdx.y;
    const int ib  = blockIdx.x;
    const int i0  = ib * ITILE;
    const int tid = threadIdx.x;

    const int lane = tid & 31, warp = tid >> 5;
    const int gid = lane >> 2;      // fragment row selector
    const int tig = lane & 3;       // fragment col selector
    const int wbase = warp * 32;    // 8 warps x 32 b-rows

    const float bsum = g_bsum[ib * J_ + j];

    // Poly constants (deg-7 odd tanh fit, clamp +-1.2998)
    const __half2 C1  = __float2half2_rn(0.999820f);
    const __half2 C3  = __float2half2_rn(-0.327971f);
    const __half2 C5  = __float2half2_rn(0.110124f);
    const __half2 C7  = __float2half2_rn(-0.020140f);
    const __half2 CLP = __float2half2_rn(1.2998f);
    const __half2 CLN = __float2half2_rn(-1.2998f);

    float acc[2][4] = {};           // [m-tile][k16-MMA D regs]
    const unsigned zero = 0;

    const __half* fbase = g_feats_h + (size_t)i0 * (B_ * FP_)
                        + (wbase + gid) * FP_ + tig * 2;

    #pragma unroll
    for (int il = 0; il < ITILE; il++) {
        const int ij = (i0 + il) * J_ + j;

        // Weight fragments: one LDG.128 each (L1-broadcast across warps)
        uint4 wq = g_w1p[ij * 32 + gid * 4 + tig];  // x..w = wf for h-groups 0..3
        uint4 bq = g_w2p[ij * 4 + tig];             // x..w = wb for h-groups 0..3

        // A fragments for both m-tiles (coalesced; L2-hot)
        const __half* fi = fbase + il * (B_ * FP_);
        unsigned A0[2], A1[2];
        #pragma unroll
        for (int mt = 0; mt < 2; mt++) {
            A0[mt] = *reinterpret_cast<const unsigned*>(fi + mt * 16 * FP_);
            A1[mt] = *reinterpret_cast<const unsigned*>(fi + (mt * 16 + 8) * FP_);
        }

        #pragma unroll
        for (int hgp = 0; hgp < 2; hgp++) {
            unsigned wf0 = hgp ? wq.z : wq.x;
            unsigned wf1 = hgp ? wq.w : wq.y;
            unsigned wb0 = hgp ? bq.z : bq.x;
            unsigned wb1 = hgp ? bq.w : bq.y;

            #pragma unroll
            for (int mt = 0; mt < 2; mt++) {
                // u-MMA, fp16 accumulator: D regs are f16x2
                unsigned u0, u1, u2, u3;
                asm volatile(
                    "mma.sync.aligned.m16n8k8.row.col.f16.f16.f16.f16 "
                    "{%0,%1}, {%2,%3}, {%4}, {%5,%6};"
                    : "=r"(u0), "=r"(u1)
                    : "r"(A0[mt]), "r"(A1[mt]), "r"(wf0), "r"(zero), "r"(zero));
                asm volatile(
                    "mma.sync.aligned.m16n8k8.row.col.f16.f16.f16.f16 "
                    "{%0,%1}, {%2,%3}, {%4}, {%5,%6};"
                    : "=r"(u2), "=r"(u3)
                    : "r"(A0[mt]), "r"(A1[mt]), "r"(wf1), "r"(zero), "r"(zero));

                // silu(t) = u + u*tanh(u), u = t/2 — pipe-split:
                // (u0,u1) on FMA pipe (polynomial), (u2,u3) on XU (tanh.approx)
                unsigned s0 = silu_poly(u0, C1, C3, C5, C7, CLP, CLN);
                unsigned s1 = silu_poly(u1, C1, C3, C5, C7, CLP, CLN);
                unsigned s2 = hfma2u(u2, tanh2u(u2), u2);
                unsigned s3 = hfma2u(u3, tanh2u(u3), u3);

                // h-contraction: m16n8k16, B = W2 replicated over n, fp32 acc
                asm volatile(
                    "mma.sync.aligned.m16n8k16.row.col.f32.f16.f16.f32 "
                    "{%0,%1,%2,%3}, {%4,%5,%6,%7}, {%8,%9}, {%0,%1,%2,%3};"
                    : "+f"(acc[mt][0]), "+f"(acc[mt][1]),
                      "+f"(acc[mt][2]), "+f"(acc[mt][3])
                    : "r"(s0), "r"(s1), "r"(s2), "r"(s3), "r"(wb0), "r"(wb1));
            }
        }
    }

    // Epilogue: tig==0 lanes hold per-b sums. Atomic-accumulate into out[b*J + j].
    if (tig == 0) {
        #pragma unroll
        for (int mt = 0; mt < 2; mt++) {
            int brow = wbase + mt * 16 + gid;
            atomicAdd(&out[(size_t)brow * J_ + j],       acc[mt][0] + bsum);
            atomicAdd(&out[(size_t)(brow + 8) * J_ + j], acc[mt][2] + bsum);
        }
    }
}

extern "C" void kernel_launch(void* const* d_in, const int* in_sizes, int n_in,
                              void* d_out, int out_size) {
    const float* x  = (const float*)d_in[0];
    const float* W1 = (const float*)d_in[1];
    const float* W2 = (const float*)d_in[2];
    const float* B1 = (const float*)d_in[3];
    const float* B2 = (const float*)d_in[4];
    float* out = (float*)d_out;

    prep_kernel<<<PREP_D, 256>>>(x, W1, W2, B1, B2, out);
    kan_main_kernel<<<dim3(IBLKS, J_), 256>>>(out);
}